// round 1
// baseline (speedup 1.0000x reference)
#include <cuda_runtime.h>
#include <cstdint>
#include <cstddef>

#define BATCH 64
#define SEQ   512
#define DIM   512
#define HID   256
#define NK    32

// ---------------- scratch (__device__ globals; no allocation) ----------------
__device__ float g_xp[(size_t)BATCH * SEQ * 2048];          // 256 MiB: xp[m=(b*512+t)][g2]
__device__ float g_hout[(size_t)2 * SEQ * HID * BATCH];     // 64 MiB:  [dir][t][j][b]
__device__ float g_hbuf[2 * 2 * HID * BATCH];               // [dir][buf][k][b]
__device__ unsigned g_bar_count = 0;
__device__ unsigned g_bar_phase = 0;

// ---------------- grid barrier (all 128 CTAs co-resident) ----------------
__device__ __forceinline__ void grid_barrier(unsigned nb)
{
    __threadfence();
    __syncthreads();
    if (threadIdx.x == 0) {
        volatile unsigned* vph = &g_bar_phase;
        unsigned ph = *vph;
        unsigned old = atomicAdd(&g_bar_count, 1u);
        if (old == nb - 1u) {
            atomicExch(&g_bar_count, 0u);
            __threadfence();
            atomicAdd(&g_bar_phase, 1u);
        } else {
            while (*vph == ph) { }
        }
    }
    __syncthreads();
}

// ---------------- Kernel 1: xp = x @ [Wih_f;Wih_b]^T + bias ----------------
// A = x (32768 x 512, row-major), B = W (2048 x 512, row-major), C = A*B^T (32768 x 2048)
__global__ __launch_bounds__(256) void sgemm_xp_kernel(
    const float* __restrict__ X, const float* __restrict__ Wf,
    const float* __restrict__ Wb, const float* __restrict__ bf,
    const float* __restrict__ bb)
{
    __shared__ float As[2][8 * 132];
    __shared__ float Bs[2][8 * 132];

    const int nTile = blockIdx.x;   // 0..15
    const int mTile = blockIdx.y;   // 0..255
    const float* W; const float* bias; int nOff;
    if (nTile < 8) { W = Wf; bias = bf; nOff = nTile * 128; }
    else           { W = Wb; bias = bb; nOff = (nTile - 8) * 128; }

    const int tid = threadIdx.x;
    const int lr = tid >> 1;            // 0..127
    const int lc = (tid & 1) * 4;       // 0 or 4
    const float* Aptr = X + (size_t)(mTile * 128 + lr) * DIM + lc;
    const float* Bptr = W + (size_t)(nOff + lr) * DIM + lc;

    const int tx = (tid & 15) * 8;      // n offset within tile
    const int ty = (tid >> 4) * 8;      // m offset within tile

    float acc[8][8];
#pragma unroll
    for (int i = 0; i < 8; i++)
#pragma unroll
        for (int j = 0; j < 8; j++) acc[i][j] = 0.f;

    float4 a4 = *(const float4*)Aptr;
    float4 b4 = *(const float4*)Bptr;
    As[0][(lc + 0) * 132 + lr] = a4.x; As[0][(lc + 1) * 132 + lr] = a4.y;
    As[0][(lc + 2) * 132 + lr] = a4.z; As[0][(lc + 3) * 132 + lr] = a4.w;
    Bs[0][(lc + 0) * 132 + lr] = b4.x; Bs[0][(lc + 1) * 132 + lr] = b4.y;
    Bs[0][(lc + 2) * 132 + lr] = b4.z; Bs[0][(lc + 3) * 132 + lr] = b4.w;
    __syncthreads();

    for (int kt = 0; kt < 64; kt++) {
        const int cur = kt & 1;
        if (kt < 63) {
            a4 = *(const float4*)(Aptr + (kt + 1) * 8);
            b4 = *(const float4*)(Bptr + (kt + 1) * 8);
        }
#pragma unroll
        for (int k = 0; k < 8; k++) {
            float ra[8], rb[8];
            *(float4*)&ra[0] = *(const float4*)&As[cur][k * 132 + ty];
            *(float4*)&ra[4] = *(const float4*)&As[cur][k * 132 + ty + 4];
            *(float4*)&rb[0] = *(const float4*)&Bs[cur][k * 132 + tx];
            *(float4*)&rb[4] = *(const float4*)&Bs[cur][k * 132 + tx + 4];
#pragma unroll
            for (int i = 0; i < 8; i++)
#pragma unroll
                for (int j = 0; j < 8; j++) acc[i][j] += ra[i] * rb[j];
        }
        if (kt < 63) {
            const int nx = cur ^ 1;
            As[nx][(lc + 0) * 132 + lr] = a4.x; As[nx][(lc + 1) * 132 + lr] = a4.y;
            As[nx][(lc + 2) * 132 + lr] = a4.z; As[nx][(lc + 3) * 132 + lr] = a4.w;
            Bs[nx][(lc + 0) * 132 + lr] = b4.x; Bs[nx][(lc + 1) * 132 + lr] = b4.y;
            Bs[nx][(lc + 2) * 132 + lr] = b4.z; Bs[nx][(lc + 3) * 132 + lr] = b4.w;
            __syncthreads();
        }
    }

    float rbias[8];
#pragma unroll
    for (int j = 0; j < 8; j++) rbias[j] = bias[nOff + tx + j];

#pragma unroll
    for (int i = 0; i < 8; i++) {
        size_t m = (size_t)(mTile * 128 + ty + i);
        float4 v0, v1;
        v0.x = acc[i][0] + rbias[0]; v0.y = acc[i][1] + rbias[1];
        v0.z = acc[i][2] + rbias[2]; v0.w = acc[i][3] + rbias[3];
        v1.x = acc[i][4] + rbias[4]; v1.y = acc[i][5] + rbias[5];
        v1.z = acc[i][6] + rbias[6]; v1.w = acc[i][7] + rbias[7];
        *(float4*)&g_xp[m * 2048 + nTile * 128 + tx]     = v0;
        *(float4*)&g_xp[m * 2048 + nTile * 128 + tx + 4] = v1;
    }
}

// ---------------- Kernel 2: persistent biLSTM recurrence ----------------
// 128 CTAs x 128 threads. CTA (dir, s) owns h-indices [4s, 4s+4) => 16 gate rows.
__global__ __launch_bounds__(128) void lstm_kernel(
    const float* __restrict__ Whh_f, const float* __restrict__ Whh_b,
    const int* __restrict__ lengths)
{
    __shared__ float Wsm[16 * 257];
    __shared__ float hsm[2][32 * 64];
    __shared__ float gsm[16 * 64];
    __shared__ float csm[4 * 64];
    __shared__ int   len_sm[64];

    const int tid = threadIdx.x;
    const int cta = blockIdx.x;
    const int dir = cta >> 6;
    const int s   = cta & 63;
    const int s4  = s * 4;
    const float* Whh = dir ? Whh_b : Whh_f;

    for (int idx = tid; idx < 16 * 256; idx += 128) {
        int ri = idx >> 8, k = idx & 255;
        int q = ri >> 2, j = ri & 3;
        Wsm[ri * 257 + k] = Whh[(q * 256 + s4 + j) * 256 + k];
    }
    if (tid < 64) len_sm[tid] = lengths[tid];
    for (int idx = tid; idx < 256; idx += 128) csm[idx] = 0.f;

    // zero my rows of hbuf[dir][0]
    {
        float* hb0 = g_hbuf + (dir * 2 + 0) * HID * BATCH;
        for (int idx = tid; idx < 4 * 64; idx += 128) {
            int j = idx >> 6, b = idx & 63;
            hb0[(s4 + j) * 64 + b] = 0.f;
        }
    }
    grid_barrier(gridDim.x);

    const int rp  = tid >> 4;       // 0..7 (row pair)
    const int bq  = tid & 15;       // 0..15 (batch quad)
    const int ri0 = rp * 2, ri1 = rp * 2 + 1;
    int col0, col1;
    { int q0 = ri0 >> 2, j0 = ri0 & 3; col0 = dir * 1024 + q0 * 256 + s4 + j0;
      int q1 = ri1 >> 2, j1 = ri1 & 3; col1 = dir * 1024 + q1 * 256 + s4 + j1; }

    for (int st = 0; st < SEQ; st++) {
        const int tstep = dir ? (SEQ - 1 - st) : st;
        const int gbuf  = st & 1;
        const float* hgl  = g_hbuf + (dir * 2 + gbuf) * HID * BATCH;
        float*       hgln = g_hbuf + (dir * 2 + (gbuf ^ 1)) * HID * BATCH;

        float acc[2][4];
#pragma unroll
        for (int bb = 0; bb < 4; bb++) {
            size_t m = (size_t)(bq * 4 + bb) * SEQ + tstep;
            acc[0][bb] = __ldg(&g_xp[m * 2048 + col0]);
            acc[1][bb] = __ldg(&g_xp[m * 2048 + col1]);
        }

        // chunked, double-buffered h load (8 chunks of 32 k-rows)
        float4 pf[4];
#pragma unroll
        for (int r = 0; r < 4; r++)
            pf[r] = __ldcg(((const float4*)hgl) + tid + r * 128);
#pragma unroll
        for (int r = 0; r < 4; r++) ((float4*)hsm[0])[tid + r * 128] = pf[r];
        __syncthreads();

        for (int cc = 0; cc < 8; cc++) {
            const int cb = cc & 1;
            if (cc < 7) {
#pragma unroll
                for (int r = 0; r < 4; r++)
                    pf[r] = __ldcg(((const float4*)hgl) + (cc + 1) * 512 + tid + r * 128);
            }
            const float* hrow = hsm[cb];
#pragma unroll
            for (int kk = 0; kk < 32; kk++) {
                const int kg = cc * 32 + kk;
                float w0 = Wsm[ri0 * 257 + kg];
                float w1 = Wsm[ri1 * 257 + kg];
                float4 h4 = *(const float4*)&hrow[kk * 64 + bq * 4];
                acc[0][0] += w0 * h4.x; acc[0][1] += w0 * h4.y;
                acc[0][2] += w0 * h4.z; acc[0][3] += w0 * h4.w;
                acc[1][0] += w1 * h4.x; acc[1][1] += w1 * h4.y;
                acc[1][2] += w1 * h4.z; acc[1][3] += w1 * h4.w;
            }
            if (cc < 7) {
#pragma unroll
                for (int r = 0; r < 4; r++) ((float4*)hsm[cb ^ 1])[tid + r * 128] = pf[r];
            }
            __syncthreads();
        }

#pragma unroll
        for (int bb = 0; bb < 4; bb++) {
            gsm[ri0 * 64 + bq * 4 + bb] = acc[0][bb];
            gsm[ri1 * 64 + bq * 4 + bb] = acc[1][bb];
        }
        __syncthreads();

#pragma unroll
        for (int r = 0; r < 2; r++) {
            const int it = tid + r * 128;
            const int j = it >> 6, b = it & 63;
            float gi = gsm[(0 * 4 + j) * 64 + b];
            float gf = gsm[(1 * 4 + j) * 64 + b];
            float gg = gsm[(2 * 4 + j) * 64 + b];
            float go = gsm[(3 * 4 + j) * 64 + b];
            float i_ = 1.f / (1.f + expf(-gi));
            float f_ = 1.f / (1.f + expf(-gf));
            float o_ = 1.f / (1.f + expf(-go));
            float g_ = tanhf(gg);
            float c_old = csm[j * 64 + b];
            float c_new = f_ * c_old + i_ * g_;
            float h_new = o_ * tanhf(c_new);
            bool  m = (tstep < len_sm[b]);
            float h_old = __ldcg(&hgl[(s4 + j) * 64 + b]);
            float c_out = m ? c_new : c_old;
            float h_out = m ? h_new : h_old;
            csm[j * 64 + b] = c_out;
            __stcg(&hgln[(s4 + j) * 64 + b], h_out);
            g_hout[((size_t)(dir * SEQ + tstep) * HID + (s4 + j)) * 64 + b] = h_out;
        }
        grid_barrier(gridDim.x);
    }
}

// ---------------- Kernel 3: logits = [h_f;h_b] @ W_clf^T + b_clf ----------------
__global__ __launch_bounds__(256) void clf_kernel(
    const float* __restrict__ Wclf, const float* __restrict__ bclf,
    float* __restrict__ out)
{
    __shared__ float Ws[32 * 65];
    __shared__ float hs[64 * 64];
    const int t   = blockIdx.x;
    const int tid = threadIdx.x;
    const int n   = tid & 31;
    const int bg  = tid >> 5;     // 0..7 -> batches bg*8..bg*8+7

    float acc[8];
#pragma unroll
    for (int i = 0; i < 8; i++) acc[i] = 0.f;

    for (int ch = 0; ch < 8; ch++) {
        const int dir = ch >> 2;
        const int jbase = (ch & 3) * 64;
        for (int l = tid; l < 2048; l += 256) {
            int nn = l >> 6, jj = l & 63;
            Ws[nn * 65 + jj] = Wclf[nn * 512 + dir * 256 + jbase + jj];
        }
        const float* hsrc = g_hout + ((size_t)(dir * SEQ + t) * HID + jbase) * 64;
#pragma unroll
        for (int r = 0; r < 4; r++)
            ((float4*)hs)[tid + r * 256] = __ldg(((const float4*)hsrc) + tid + r * 256);
        __syncthreads();
#pragma unroll 16
        for (int jj = 0; jj < 64; jj++) {
            float w = Ws[n * 65 + jj];
            float4 hA = *(const float4*)&hs[jj * 64 + bg * 8];
            float4 hB = *(const float4*)&hs[jj * 64 + bg * 8 + 4];
            acc[0] += w * hA.x; acc[1] += w * hA.y; acc[2] += w * hA.z; acc[3] += w * hA.w;
            acc[4] += w * hB.x; acc[5] += w * hB.y; acc[6] += w * hB.z; acc[7] += w * hB.w;
        }
        __syncthreads();
    }
    const float bias = bclf[n];
#pragma unroll
    for (int bb = 0; bb < 8; bb++) {
        int b = bg * 8 + bb;
        out[((size_t)b * SEQ + t) * NK + n] = acc[bb] + bias;
    }
}

// ---------------- Kernel 4: Viterbi decode (1 warp per batch) ----------------
__global__ __launch_bounds__(32) void viterbi_kernel(
    const float* __restrict__ logits, const int* __restrict__ lengths,
    const float* __restrict__ startt, const float* __restrict__ endt,
    const float* __restrict__ trans, float* __restrict__ preds, int write_preds)
{
    __shared__ unsigned char hist[511][32];
    const int b = blockIdx.x;
    const int j = threadIdx.x;
    const int len = lengths[b];

    float tcol[32];
#pragma unroll
    for (int i = 0; i < 32; i++) tcol[i] = trans[i * 32 + j];

    const float* lg = logits + (size_t)b * SEQ * NK;
    float score = startt[j] + lg[j];

    for (int t = 1; t < SEQ; t++) {
        float e = lg[t * NK + j];
        float best = -3.4e38f; int arg = 0;
#pragma unroll
        for (int i = 0; i < 32; i++) {
            float si = __shfl_sync(0xffffffffu, score, i);
            float v = (si + tcol[i]) + e;
            if (v > best) { best = v; arg = i; }
        }
        bool m = (t < len);
        hist[t - 1][j] = (unsigned char)(m ? arg : j);
        score = m ? best : score;
    }
    score += endt[j];

    // first-max argmax across warp (matches jnp.argmax tie-breaking)
    float bv = score; int bi = j;
#pragma unroll
    for (int off = 16; off; off >>= 1) {
        float ov = __shfl_xor_sync(0xffffffffu, bv, off);
        int   oi = __shfl_xor_sync(0xffffffffu, bi, off);
        if (ov > bv || (ov == bv && oi < bi)) { bv = ov; bi = oi; }
    }
    __syncwarp();

    if (write_preds && j == 0) {
        int tag = bi;
        float* pp = preds + (size_t)b * SEQ;
        for (int t = SEQ - 2; t >= 0; t--) {
            pp[t + 1] = (float)(((t + 1) < len) ? tag : 0);
            tag = hist[t][tag];
        }
        pp[0] = (float)((0 < len) ? tag : 0);
    }
}

// ---------------- launch ----------------
extern "C" void kernel_launch(void* const* d_in, const int* in_sizes, int n_in,
                              void* d_out, int out_size)
{
    const float* x     = (const float*)d_in[0];
    const int*   lens  = (const int*)d_in[1];
    // d_in[2] = mask (recomputed from lengths; unused)
    const float* Wih_f = (const float*)d_in[3];
    const float* Whh_f = (const float*)d_in[4];
    const float* b_f   = (const float*)d_in[5];
    const float* Wih_b = (const float*)d_in[6];
    const float* Whh_b = (const float*)d_in[7];
    const float* b_b   = (const float*)d_in[8];
    const float* W_clf = (const float*)d_in[9];
    const float* b_clf = (const float*)d_in[10];
    const float* st_t  = (const float*)d_in[11];
    const float* en_t  = (const float*)d_in[12];
    const float* trans = (const float*)d_in[13];
    float* out = (float*)d_out;

    sgemm_xp_kernel<<<dim3(16, 256), 256>>>(x, Wih_f, Wih_b, b_f, b_b);
    lstm_kernel<<<128, 128>>>(Whh_f, Whh_b, lens);
    clf_kernel<<<512, 256>>>(W_clf, b_clf, out);

    const int logits_elems = BATCH * SEQ * NK;      // 1048576
    const int preds_elems  = BATCH * SEQ;           // 32768
    int wp = (out_size >= logits_elems + preds_elems) ? 1 : 0;
    viterbi_kernel<<<64, 32>>>(out, lens, st_t, en_t, trans, out + logits_elems, wp);
}